// round 2
// baseline (speedup 1.0000x reference)
#include <cuda_runtime.h>
#include <cuda_bf16.h>
#include <cstdint>

#define CIN   256
#define EDIM  16
#define LWIN  64
#define MDIM  64
#define HDIM  64
#define COUT  256
#define BATCH 16
#define NSTEP 2048

// ---------------- scratch (static device allocations, allowed) ----------------
__device__ float g_TW[CIN * LWIN * HDIM];      // 4 MB: per-(token,pos) W-path contribution
__device__ float g_Tb[CIN * LWIN * HDIM];      // 4 MB: b-path
__device__ float g_preW[NSTEP * BATCH * HDIM]; // 8 MB
__device__ float g_preb[NSTEP * BATCH * HDIM]; // 8 MB
__device__ float g_m[NSTEP * BATCH * MDIM];    // 8 MB: stored states for loss epilogue

__device__ __forceinline__ float sigmoidf_fast(float x) {
    return 1.0f / (1.0f + __expf(-x));
}

// ---------------- kernel 1: token/position contribution tables ----------------
__global__ void table_kernel(const float* __restrict__ emb,
                             const float* __restrict__ Wew,
                             const float* __restrict__ bew) {
    int c = blockIdx.x >> 6;
    int l = blockIdx.x & 63;
    int h = threadIdx.x;
    float aw = 0.f, ab = 0.f;
#pragma unroll
    for (int e = 0; e < EDIM; ++e) {
        float ev = emb[c * EDIM + e];
        int row = MDIM + l * EDIM + e;
        aw += ev * Wew[row * HDIM + h];
        ab += ev * bew[row * HDIM + h];
    }
    g_TW[(c * LWIN + l) * HDIM + h] = aw;
    g_Tb[(c * LWIN + l) * HDIM + h] = ab;
}

// ---------------- kernel 2: window pre-activations (no bias) ----------------
__global__ void pre_kernel(const int* __restrict__ x0) {
    int tb = blockIdx.x;
    int t = tb >> 4, b = tb & 15;
    int h = threadIdx.x;
    float aw = 0.f, ab = 0.f;
#pragma unroll 4
    for (int l = 0; l < LWIN; ++l) {
        int k = t + l;  // index into padded sequence xp
        int tok = (k < LWIN) ? 0 : x0[b * NSTEP + (k - LWIN)];
        aw += g_TW[(tok * LWIN + l) * HDIM + h];
        ab += g_Tb[(tok * LWIN + l) * HDIM + h];
    }
    g_preW[(t * BATCH + b) * HDIM + h] = aw;
    g_preb[(t * BATCH + b) * HDIM + h] = ab;
}

// ---------------- kernel 3: sequential scan ----------------
// Grid: 128 CTAs = 16 clusters (one per batch) x 8 CTAs (i-slices of 8).
// 512 threads/CTA. W_dec_w slice lives in registers (wd[64] per thread).
__global__ void __launch_bounds__(512, 1)
scan_kernel(const float* __restrict__ Wew, const float* __restrict__ Web,
            const float* __restrict__ Wdw, const float* __restrict__ Wdb,
            const float* __restrict__ bew, const float* __restrict__ beb,
            const float* __restrict__ bdw, const float* __restrict__ bdb) {
    __shared__ float sM[2][MDIM];     // ping-pong full m for this batch
    __shared__ float sH[2][HDIM];     // hW, hb
    __shared__ float sP[4 * 128];     // enc partials
    __shared__ float sRed[16];        // per-warp partials of bilinear
    __shared__ float sBm[8];          // bm for my 8 i's
    __shared__ float sBdp[8 * 65];    // b_dec_w slice [il][h], padded stride

    const int tid = threadIdx.x;
    const int b = blockIdx.x >> 3;    // batch = cluster id
    const int r = blockIdx.x & 7;     // cluster rank = i-slice

    const int il = tid >> 6, j = tid & 63;
    const int ig = r * 8 + il;

    // bilinear weight slice in registers: wd[h] = W_dec_w[h, ig*64 + j]
    float wd[64];
#pragma unroll
    for (int h = 0; h < 64; ++h)
        wd[h] = Wdw[h * 4096 + ig * 64 + j];
    const float wdecb = Wdb[ig * 64 + j];

    // enc weight fragment in registers: thread (q, path, h6) covers j = q*16..q*16+15
    const int q = tid >> 7;
    const int rest = tid & 127;
    const int path = rest >> 6;
    const int h6 = rest & 63;
    const float* Aarr = path ? bew : Wew;
    float aenc[16];
#pragma unroll
    for (int it = 0; it < 16; ++it)
        aenc[it] = Aarr[(q * 16 + it) * 64 + h6];

    float encb = 0.f;
    const float* pp = nullptr;
    float pre_next = 0.f;
    if (tid < 128) {  // these threads finalize z and fetch pre-activations
        encb = path ? beb[h6] : Web[h6];
        pp = (path ? g_preb : g_preW) + b * 64 + h6;
        pre_next = pp[0];
    }
    float bdb_r = 0.f;
    if (tid < 64) bdb_r = bdb[r * 8 + (tid >> 3)];

    // b_dec_w slice into padded smem
    {
        int bil = tid >> 6, hh = tid & 63;
        sBdp[bil * 65 + hh] = bdw[hh * 64 + r * 8 + bil];
    }
    if (tid < 64) sM[0][tid] = 0.f;
    __syncthreads();
    asm volatile("barrier.cluster.arrive.aligned;\n" ::: "memory");
    asm volatile("barrier.cluster.wait.aligned;\n" ::: "memory");

#pragma unroll 1
    for (int t = 0; t < NSTEP; ++t) {
        const float* mcur = sM[t & 1];
        float pre_cur = pre_next;

        // stage 1: enc partial dot (4 threads per output)
        float acc = 0.f;
#pragma unroll
        for (int it = 0; it < 16; ++it)
            acc += mcur[q * 16 + it] * aenc[it];
        sP[q * 128 + rest] = acc;
        __syncthreads();

        // stage 2: finalize z, sigmoid, publish hW/hb; prefetch next pre
        if (tid < 128) {
            float z = sP[rest] + sP[128 + rest] + sP[256 + rest] + sP[384 + rest]
                    + pre_cur + encb;
            sH[path][h6] = sigmoidf_fast(z);
            if (t + 1 < NSTEP) pre_next = pp[(t + 1) * (BATCH * 64)];
        }
        __syncthreads();

        // stage 3a (warps 0-1): bm[i] = hb . b_dec_w[:, ig] + b_dec_b[ig]
        if (tid < 64) {
            int bil = tid >> 3, s8 = tid & 7;
            float p = 0.f;
#pragma unroll
            for (int kk = 0; kk < 8; ++kk) {
                int hh = s8 * 8 + kk;
                p += sH[1][hh] * sBdp[bil * 65 + hh];
            }
            p += __shfl_xor_sync(0xffffffffu, p, 1);
            p += __shfl_xor_sync(0xffffffffu, p, 2);
            p += __shfl_xor_sync(0xffffffffu, p, 4);
            if (s8 == 0) sBm[bil] = p + bdb_r;
        }

        // stage 3b (all): bilinear. Wm[ig,j] = hW . wd + Wdb; val = Wm*m[j]
        float mj = mcur[j];
        float acc2 = 0.f;
        const float* hw = sH[0];
#pragma unroll
        for (int c4 = 0; c4 < 16; ++c4) {
            float4 hv = *(const float4*)(hw + c4 * 4);
            acc2 += hv.x * wd[c4 * 4 + 0] + hv.y * wd[c4 * 4 + 1]
                  + hv.z * wd[c4 * 4 + 2] + hv.w * wd[c4 * 4 + 3];
        }
        float val = (acc2 + wdecb) * mj;
#pragma unroll
        for (int off = 16; off; off >>= 1)
            val += __shfl_xor_sync(0xffffffffu, val, off);
        if ((tid & 31) == 0) sRed[tid >> 5] = val;
        __syncthreads();

        // stage 4: finish m[i], broadcast to cluster peers, persist state
        if (tid < 8) {
            float tot = sRed[tid * 2] + sRed[tid * 2 + 1] + sBm[tid];
            float nm = sigmoidf_fast(tot);
            int nxt = (t + 1) & 1;
            int igo = r * 8 + tid;
            sM[nxt][igo] = nm;
            g_m[(t * BATCH + b) * MDIM + igo] = nm;
            uint32_t a = (uint32_t)__cvta_generic_to_shared(&sM[nxt][igo]);
#pragma unroll
            for (int p2 = 0; p2 < 8; ++p2) {
                if (p2 == r) continue;
                uint32_t ra;
                asm volatile("mapa.shared::cluster.u32 %0, %1, %2;"
                             : "=r"(ra) : "r"(a), "r"(p2));
                asm volatile("st.shared::cluster.f32 [%0], %1;"
                             :: "r"(ra), "f"(nm) : "memory");
            }
        }
        // release ordering of the cluster-shared stores + full cluster barrier
        asm volatile("barrier.cluster.arrive.aligned;\n" ::: "memory");
        asm volatile("barrier.cluster.wait.aligned;\n" ::: "memory");
    }
}

// ---------------- kernel 4: loss epilogue (parallel over all t,b) ----------------
__global__ void __launch_bounds__(256)
loss_kernel(const int* __restrict__ x0, const float* __restrict__ decw,
            const float* __restrict__ decb, float* __restrict__ out) {
    __shared__ float sm[64];
    __shared__ float sred[8];
    __shared__ float syl;
    int row = blockIdx.x;            // row = t*16 + b == output index
    int t = row >> 4, b = row & 15;
    int c = threadIdx.x;
    if (c < 64) sm[c] = g_m[row * 64 + c];
    __syncthreads();

    float logit = decb[c];
#pragma unroll
    for (int i = 0; i < 64; ++i)
        logit += sm[i] * decw[i * COUT + c];

    int y = x0[b * NSTEP + t];
    if (c == y) syl = logit;

    // block max
    float mx = logit;
#pragma unroll
    for (int off = 16; off; off >>= 1)
        mx = fmaxf(mx, __shfl_xor_sync(0xffffffffu, mx, off));
    if ((c & 31) == 0) sred[c >> 5] = mx;
    __syncthreads();
    mx = sred[0];
#pragma unroll
    for (int w = 1; w < 8; ++w) mx = fmaxf(mx, sred[w]);

    // block sum of exp
    float ex = __expf(logit - mx);
#pragma unroll
    for (int off = 16; off; off >>= 1)
        ex += __shfl_xor_sync(0xffffffffu, ex, off);
    __syncthreads();
    if ((c & 31) == 0) sred[c >> 5] = ex;
    __syncthreads();
    if (c == 0) {
        float S = 0.f;
#pragma unroll
        for (int w = 0; w < 8; ++w) S += sred[w];
        float lse = mx + __logf(S);
        out[row] = (lse - syl) * 1.4426950408889634f;  // 1/ln(2)
    }
}

// ---------------- launch ----------------
extern "C" void kernel_launch(void* const* d_in, const int* in_sizes, int n_in,
                              void* d_out, int out_size) {
    const int*   x0   = (const int*)d_in[0];
    const float* emb  = (const float*)d_in[1];
    const float* Wew  = (const float*)d_in[2];
    const float* Web  = (const float*)d_in[3];
    const float* Wdw  = (const float*)d_in[4];
    const float* Wdb  = (const float*)d_in[5];
    const float* bew  = (const float*)d_in[6];
    const float* beb  = (const float*)d_in[7];
    const float* bdw  = (const float*)d_in[8];
    const float* bdb  = (const float*)d_in[9];
    const float* decw = (const float*)d_in[10];
    const float* decb = (const float*)d_in[11];
    float* out = (float*)d_out;

    table_kernel<<<CIN * LWIN, 64>>>(emb, Wew, bew);
    pre_kernel<<<NSTEP * BATCH, 64>>>(x0);

    cudaLaunchConfig_t cfg = {};
    cfg.gridDim = dim3(128, 1, 1);
    cfg.blockDim = dim3(512, 1, 1);
    cfg.dynamicSmemBytes = 0;
    cfg.stream = 0;
    cudaLaunchAttribute attr[1];
    attr[0].id = cudaLaunchAttributeClusterDimension;
    attr[0].val.clusterDim.x = 8;
    attr[0].val.clusterDim.y = 1;
    attr[0].val.clusterDim.z = 1;
    cfg.attrs = attr;
    cfg.numAttrs = 1;
    cudaLaunchKernelEx(&cfg, scan_kernel, Wew, Web, Wdw, Wdb, bew, beb, bdw, bdb);

    loss_kernel<<<NSTEP * BATCH, 256>>>(x0, decw, decb, out);
}